// round 4
// baseline (speedup 1.0000x reference)
#include <cuda_runtime.h>
#include <cstdint>
#include <math.h>

#define TOKENS 512
#define HDIM   2048
#define NEXP   60
#define IDIM   1408
#define SDIM   5632
#define TOPK   4

// ---------------- scratch (device globals: no allocation allowed) ----------------
__device__ __align__(16) float g_act[(size_t)NEXP * TOKENS * IDIM];  // ~173 MB
__device__ __align__(16) float g_up[(size_t)TOKENS * SDIM];          // ~11.5 MB
__device__ int   g_cnt[NEXP];
__device__ int   g_tok[NEXP * TOKENS];
__device__ float g_wgt[NEXP * TOKENS];
__device__ float g_gate[TOKENS];

// ---------------- helpers ----------------
__device__ __forceinline__ uint32_t f2tf(float f) {
    uint32_t r;
    asm("cvt.rna.tf32.f32 %0, %1;" : "=r"(r) : "f"(f));
    return r;
}

__device__ __forceinline__ void mma8(float& d0, float& d1, float& d2, float& d3,
                                     uint32_t a0, uint32_t a1, uint32_t a2, uint32_t a3,
                                     uint32_t b0, uint32_t b1) {
    asm volatile(
        "mma.sync.aligned.m16n8k8.row.col.f32.tf32.tf32.f32 "
        "{%0,%1,%2,%3},{%4,%5,%6,%7},{%8,%9},{%0,%1,%2,%3};\n"
        : "+f"(d0), "+f"(d1), "+f"(d2), "+f"(d3)
        : "r"(a0), "r"(a1), "r"(a2), "r"(a3), "r"(b0), "r"(b1));
}

// ---------------- init ----------------
__global__ void zero_kernel(float* out, int n) {
    int i = blockIdx.x * blockDim.x + threadIdx.x;
    if (i < n) out[i] = 0.f;
    if (blockIdx.x == 0 && threadIdx.x < NEXP) g_cnt[threadIdx.x] = 0;
}

// ---------------- router: logits -> softmax -> top4 -> expert lists ----------------
__global__ void router_kernel(const float* __restrict__ x,
                              const float* __restrict__ gw,
                              const float* __restrict__ sgw) {
    int t = blockIdx.x;
    __shared__ float sl[NEXP];
    __shared__ float ssg;
    int e = threadIdx.x;
    const float* xr = x + (size_t)t * HDIM;
    if (e < NEXP) {
        float acc = 0.f;
        for (int k = 0; k < HDIM; k++) acc += xr[k] * gw[(size_t)k * NEXP + e];
        sl[e] = acc;
    } else if (e == NEXP) {
        float acc = 0.f;
        for (int k = 0; k < HDIM; k++) acc += xr[k] * sgw[k];
        ssg = acc;
    }
    __syncthreads();
    if (threadIdx.x == 0) {
        float mx = -1e30f;
        for (int i = 0; i < NEXP; i++) mx = fmaxf(mx, sl[i]);
        float sum = 0.f;
        for (int i = 0; i < NEXP; i++) { sl[i] = expf(sl[i] - mx); sum += sl[i]; }
        for (int j = 0; j < TOPK; j++) {
            int am = 0; float bv = -1.f;
            for (int i = 0; i < NEXP; i++)
                if (sl[i] > bv) { bv = sl[i]; am = i; }
            int pos = atomicAdd(&g_cnt[am], 1);
            g_tok[am * TOKENS + pos] = t;
            g_wgt[am * TOKENS + pos] = bv / sum;
            sl[am] = -1.f;
        }
        g_gate[t] = 1.f / (1.f + expf(-ssg));
    }
}

// ---------------- dual GEMM: silu(X@W1) * (X@W3) [* route weight] ----------------
// Block tile 64(M) x 64(N) x 32(K). 128 threads, 4 warps in 2x2, warp tile 32x32.
template <bool GATHER>
__global__ __launch_bounds__(128) void dual_mlp_kernel(
    const float* __restrict__ X,   // [TOKENS, HDIM]
    const float* __restrict__ W1,  // GATHER: [E, HDIM, N]   else [HDIM, N]
    const float* __restrict__ W3,
    int N) {
    const int K = HDIM;
    int e = blockIdx.z;
    int n_base = blockIdx.x * 64;
    int m_base = blockIdx.y * 64;

    int rows;
    const float* w1p;
    const float* w3p;
    float* outp;
    const int* tokp = nullptr;
    const float* wgtp = nullptr;
    if (GATHER) {
        rows = g_cnt[e];
        if (m_base >= rows) return;
        w1p = W1 + (size_t)e * K * N;
        w3p = W3 + (size_t)e * K * N;
        outp = g_act + (size_t)e * TOKENS * N;
        tokp = g_tok + e * TOKENS;
        wgtp = g_wgt + e * TOKENS;
    } else {
        rows = TOKENS;
        if (m_base >= rows) return;
        w1p = W1; w3p = W3; outp = g_up;
    }

    __shared__ float As[32][68];   // [k][m]
    __shared__ float B1s[32][68];  // [k][n]
    __shared__ float B3s[32][68];

    int tid = threadIdx.x;
    // per-thread A-load assignments (4 float4 loads covering 64x32 tile)
    const float* arow[4];
    int akk[4];
#pragma unroll
    for (int i = 0; i < 4; i++) {
        int idx = i * 128 + tid;   // 0..511
        int r = idx >> 3;          // row in tile 0..63
        akk[i] = (idx & 7) * 4;    // k offset 0..28
        int mg = m_base + r;
        if (mg < rows) {
            int src = GATHER ? tokp[mg] : mg;
            arow[i] = X + (size_t)src * K;
        } else {
            arow[i] = nullptr;
        }
    }

    int warp = tid >> 5, lane = tid & 31;
    int wm = (warp >> 1) * 32, wn = (warp & 1) * 32;
    int gid = lane >> 2, tig = lane & 3;

    float acc1[2][4][4];
    float acc3[2][4][4];
#pragma unroll
    for (int a = 0; a < 2; a++)
#pragma unroll
        for (int b = 0; b < 4; b++)
#pragma unroll
            for (int c = 0; c < 4; c++) { acc1[a][b][c] = 0.f; acc3[a][b][c] = 0.f; }

    for (int k0 = 0; k0 < K; k0 += 32) {
#pragma unroll
        for (int i = 0; i < 4; i++) {
            int idx = i * 128 + tid;
            int r = idx >> 3;
            int kk = akk[i];
            float4 v = make_float4(0.f, 0.f, 0.f, 0.f);
            if (arow[i]) v = *(const float4*)(arow[i] + k0 + kk);
            As[kk + 0][r] = __uint_as_float(f2tf(v.x));
            As[kk + 1][r] = __uint_as_float(f2tf(v.y));
            As[kk + 2][r] = __uint_as_float(f2tf(v.z));
            As[kk + 3][r] = __uint_as_float(f2tf(v.w));
        }
#pragma unroll
        for (int i = 0; i < 4; i++) {
            int idx = i * 128 + tid;
            int kk = idx >> 4;          // 0..31
            int nn = (idx & 15) * 4;    // 0..60
            size_t off = (size_t)(k0 + kk) * N + n_base + nn;
            float4 v1 = *(const float4*)(w1p + off);
            float4 v3 = *(const float4*)(w3p + off);
            B1s[kk][nn + 0] = __uint_as_float(f2tf(v1.x));
            B1s[kk][nn + 1] = __uint_as_float(f2tf(v1.y));
            B1s[kk][nn + 2] = __uint_as_float(f2tf(v1.z));
            B1s[kk][nn + 3] = __uint_as_float(f2tf(v1.w));
            B3s[kk][nn + 0] = __uint_as_float(f2tf(v3.x));
            B3s[kk][nn + 1] = __uint_as_float(f2tf(v3.y));
            B3s[kk][nn + 2] = __uint_as_float(f2tf(v3.z));
            B3s[kk][nn + 3] = __uint_as_float(f2tf(v3.w));
        }
        __syncthreads();
#pragma unroll
        for (int kb = 0; kb < 32; kb += 8) {
            uint32_t a[2][4];
#pragma unroll
            for (int ms = 0; ms < 2; ms++) {
                int mr = wm + ms * 16;
                a[ms][0] = __float_as_uint(As[kb + tig][mr + gid]);
                a[ms][1] = __float_as_uint(As[kb + tig][mr + gid + 8]);
                a[ms][2] = __float_as_uint(As[kb + tig + 4][mr + gid]);
                a[ms][3] = __float_as_uint(As[kb + tig + 4][mr + gid + 8]);
            }
#pragma unroll
            for (int ns = 0; ns < 4; ns++) {
                int nc = wn + ns * 8;
                uint32_t b10 = __float_as_uint(B1s[kb + tig][nc + gid]);
                uint32_t b11 = __float_as_uint(B1s[kb + tig + 4][nc + gid]);
                uint32_t b30 = __float_as_uint(B3s[kb + tig][nc + gid]);
                uint32_t b31 = __float_as_uint(B3s[kb + tig + 4][nc + gid]);
#pragma unroll
                for (int ms = 0; ms < 2; ms++) {
                    mma8(acc1[ms][ns][0], acc1[ms][ns][1], acc1[ms][ns][2], acc1[ms][ns][3],
                         a[ms][0], a[ms][1], a[ms][2], a[ms][3], b10, b11);
                    mma8(acc3[ms][ns][0], acc3[ms][ns][1], acc3[ms][ns][2], acc3[ms][ns][3],
                         a[ms][0], a[ms][1], a[ms][2], a[ms][3], b30, b31);
                }
            }
        }
        __syncthreads();
    }

    // epilogue: act = silu(p1) * p3 [* route weight]
#pragma unroll
    for (int ms = 0; ms < 2; ms++)
#pragma unroll
        for (int ns = 0; ns < 4; ns++)
#pragma unroll
            for (int i = 0; i < 4; i++) {
                int m = m_base + wm + ms * 16 + gid + ((i & 2) ? 8 : 0);
                int n = n_base + wn + ns * 8 + tig * 2 + (i & 1);
                if (m < rows) {
                    float p1 = acc1[ms][ns][i];
                    float p3 = acc3[ms][ns][i];
                    float v = (p1 / (1.f + expf(-p1))) * p3;
                    if (GATHER) v *= wgtp[m];
                    outp[(size_t)m * N + n] = v;
                }
            }
}

// ---------------- down projection: A @ W2 -> accumulate into out ----------------
template <bool GATHER>
__global__ __launch_bounds__(128) void down_kernel(
    const float* __restrict__ W2,  // GATHER: [E, K, HDIM] else [K, HDIM]
    float* __restrict__ out,       // [TOKENS, HDIM]
    int K) {
    const int N = HDIM;
    int e = blockIdx.z;
    int n_base = blockIdx.x * 64;
    int m_base = blockIdx.y * 64;

    int rows;
    const float* Ap;
    const float* wp;
    const int* tokp = nullptr;
    if (GATHER) {
        rows = g_cnt[e];
        if (m_base >= rows) return;
        Ap = g_act + (size_t)e * TOKENS * K;
        wp = W2 + (size_t)e * K * N;
        tokp = g_tok + e * TOKENS;
    } else {
        rows = TOKENS;
        if (m_base >= rows) return;
        Ap = g_up;
        wp = W2;
    }

    __shared__ float As[32][68];
    __shared__ float Bs[32][68];

    int tid = threadIdx.x;
    const float* arow[4];
    int akk[4];
#pragma unroll
    for (int i = 0; i < 4; i++) {
        int idx = i * 128 + tid;
        int r = idx >> 3;
        akk[i] = (idx & 7) * 4;
        int mg = m_base + r;
        arow[i] = (mg < rows) ? (Ap + (size_t)mg * K) : nullptr;
    }

    int warp = tid >> 5, lane = tid & 31;
    int wm = (warp >> 1) * 32, wn = (warp & 1) * 32;
    int gid = lane >> 2, tig = lane & 3;

    float acc[2][4][4];
#pragma unroll
    for (int a = 0; a < 2; a++)
#pragma unroll
        for (int b = 0; b < 4; b++)
#pragma unroll
            for (int c = 0; c < 4; c++) acc[a][b][c] = 0.f;

    for (int k0 = 0; k0 < K; k0 += 32) {
#pragma unroll
        for (int i = 0; i < 4; i++) {
            int idx = i * 128 + tid;
            int r = idx >> 3;
            int kk = akk[i];
            float4 v = make_float4(0.f, 0.f, 0.f, 0.f);
            if (arow[i]) v = *(const float4*)(arow[i] + k0 + kk);
            As[kk + 0][r] = __uint_as_float(f2tf(v.x));
            As[kk + 1][r] = __uint_as_float(f2tf(v.y));
            As[kk + 2][r] = __uint_as_float(f2tf(v.z));
            As[kk + 3][r] = __uint_as_float(f2tf(v.w));
        }
#pragma unroll
        for (int i = 0; i < 4; i++) {
            int idx = i * 128 + tid;
            int kk = idx >> 4;
            int nn = (idx & 15) * 4;
            size_t off = (size_t)(k0 + kk) * N + n_base + nn;
            float4 v = *(const float4*)(wp + off);
            Bs[kk][nn + 0] = __uint_as_float(f2tf(v.x));
            Bs[kk][nn + 1] = __uint_as_float(f2tf(v.y));
            Bs[kk][nn + 2] = __uint_as_float(f2tf(v.z));
            Bs[kk][nn + 3] = __uint_as_float(f2tf(v.w));
        }
        __syncthreads();
#pragma unroll
        for (int kb = 0; kb < 32; kb += 8) {
            uint32_t a[2][4];
#pragma unroll
            for (int ms = 0; ms < 2; ms++) {
                int mr = wm + ms * 16;
                a[ms][0] = __float_as_uint(As[kb + tig][mr + gid]);
                a[ms][1] = __float_as_uint(As[kb + tig][mr + gid + 8]);
                a[ms][2] = __float_as_uint(As[kb + tig + 4][mr + gid]);
                a[ms][3] = __float_as_uint(As[kb + tig + 4][mr + gid + 8]);
            }
#pragma unroll
            for (int ns = 0; ns < 4; ns++) {
                int nc = wn + ns * 8;
                uint32_t b0 = __float_as_uint(Bs[kb + tig][nc + gid]);
                uint32_t b1 = __float_as_uint(Bs[kb + tig + 4][nc + gid]);
#pragma unroll
                for (int ms = 0; ms < 2; ms++) {
                    mma8(acc[ms][ns][0], acc[ms][ns][1], acc[ms][ns][2], acc[ms][ns][3],
                         a[ms][0], a[ms][1], a[ms][2], a[ms][3], b0, b1);
                }
            }
        }
        __syncthreads();
    }

#pragma unroll
    for (int ms = 0; ms < 2; ms++)
#pragma unroll
        for (int ns = 0; ns < 4; ns++)
#pragma unroll
            for (int i = 0; i < 4; i++) {
                int m = m_base + wm + ms * 16 + gid + ((i & 2) ? 8 : 0);
                int n = n_base + wn + ns * 8 + tig * 2 + (i & 1);
                if (m < rows) {
                    float v = acc[ms][ns][i];
                    if (GATHER) {
                        atomicAdd(&out[(size_t)tokp[m] * N + n], v);
                    } else {
                        out[(size_t)m * N + n] += g_gate[m] * v;
                    }
                }
            }
}

// ---------------- launch ----------------
extern "C" void kernel_launch(void* const* d_in, const int* in_sizes, int n_in,
                              void* d_out, int out_size) {
    const float* x   = (const float*)d_in[0];
    const float* gw  = (const float*)d_in[1];
    const float* w1  = (const float*)d_in[2];
    const float* w3  = (const float*)d_in[3];
    const float* w2  = (const float*)d_in[4];
    const float* sw1 = (const float*)d_in[5];
    const float* sw3 = (const float*)d_in[6];
    const float* sw2 = (const float*)d_in[7];
    const float* sgw = (const float*)d_in[8];
    float* out = (float*)d_out;

    // zero output + per-expert counters
    zero_kernel<<<(TOKENS * HDIM + 255) / 256, 256>>>(out, TOKENS * HDIM);

    // router: top-4 routing, expert token lists, shared sigmoid gate
    router_kernel<<<TOKENS, 64>>>(x, gw, sgw);

    // routed experts: act[e, slot, I] = route_w * silu(X@w1e) * (X@w3e)
    dual_mlp_kernel<true><<<dim3(IDIM / 64, 8, NEXP), 128>>>(x, w1, w3, IDIM);

    // shared expert up: up[T, S] = silu(X@sw1) * (X@sw3)
    dual_mlp_kernel<false><<<dim3(SDIM / 64, 8, 1), 128>>>(x, sw1, sw3, SDIM);

    // routed down: out[tok] += act @ w2e (atomic scatter)
    down_kernel<true><<<dim3(HDIM / 64, 8, NEXP), 128>>>(w2, out, IDIM);

    // shared down: out[t] += sigmoid_gate[t] * (up @ sw2)
    down_kernel<false><<<dim3(HDIM / 64, 8, 1), 128>>>(sw2, out, SDIM);
}

// round 5
// speedup vs baseline: 1.9227x; 1.9227x over previous
#include <cuda_runtime.h>
#include <cstdint>
#include <math.h>

#define TOKENS 512
#define HDIM   2048
#define NEXP   60
#define IDIM   1408
#define SDIM   5632
#define TOPK   4

// ---------------- scratch (device globals: no allocation allowed) ----------------
__device__ __align__(16) float g_act[(size_t)NEXP * TOKENS * IDIM];  // ~173 MB
__device__ __align__(16) float g_up[(size_t)TOKENS * SDIM];          // ~11.5 MB
__device__ int   g_cnt[NEXP];
__device__ int   g_tok[NEXP * TOKENS];
__device__ float g_wgt[NEXP * TOKENS];
__device__ float g_gate[TOKENS];

// ---------------- helpers ----------------
__device__ __forceinline__ uint32_t f2tf(float f) {
    uint32_t r;
    asm("cvt.rna.tf32.f32 %0, %1;" : "=r"(r) : "f"(f));
    return r;
}

__device__ __forceinline__ void mma8(float& d0, float& d1, float& d2, float& d3,
                                     uint32_t a0, uint32_t a1, uint32_t a2, uint32_t a3,
                                     uint32_t b0, uint32_t b1) {
    asm volatile(
        "mma.sync.aligned.m16n8k8.row.col.f32.tf32.tf32.f32 "
        "{%0,%1,%2,%3},{%4,%5,%6,%7},{%8,%9},{%0,%1,%2,%3};\n"
        : "+f"(d0), "+f"(d1), "+f"(d2), "+f"(d3)
        : "r"(a0), "r"(a1), "r"(a2), "r"(a3), "r"(b0), "r"(b1));
}

__device__ __forceinline__ void cpa16(uint32_t dst, const float* src, uint32_t sz) {
    asm volatile("cp.async.cg.shared.global [%0], [%1], 16, %2;\n"
                 :: "r"(dst), "l"(src), "r"(sz));
}
__device__ __forceinline__ void cpa_commit() {
    asm volatile("cp.async.commit_group;\n" ::: "memory");
}
__device__ __forceinline__ void cpa_wait1() {
    asm volatile("cp.async.wait_group 1;\n" ::: "memory");
}
__device__ __forceinline__ void cpa_wait0() {
    asm volatile("cp.async.wait_group 0;\n" ::: "memory");
}
__device__ __forceinline__ uint32_t smem_u32(const void* p) {
    uint32_t r;
    asm("{ .reg .u64 t; cvta.to.shared.u64 t, %1; cvt.u32.u64 %0, t; }"
        : "=r"(r) : "l"(p));
    return r;
}

// ---------------- init ----------------
__global__ void zero_kernel(float* out, int n) {
    int i = blockIdx.x * blockDim.x + threadIdx.x;
    if (i < n) out[i] = 0.f;
    if (blockIdx.x == 0 && threadIdx.x < NEXP) g_cnt[threadIdx.x] = 0;
}

// ---------------- router ----------------
__global__ void router_kernel(const float* __restrict__ x,
                              const float* __restrict__ gw,
                              const float* __restrict__ sgw) {
    int t = blockIdx.x;
    __shared__ float sl[NEXP];
    __shared__ float ssg;
    int e = threadIdx.x;
    const float4* x4 = (const float4*)(x + (size_t)t * HDIM);
    if (e < NEXP) {
        float a0 = 0.f, a1 = 0.f, a2 = 0.f, a3 = 0.f;
        for (int k4 = 0; k4 < HDIM / 4; k4++) {
            float4 v = x4[k4];
            int k = k4 * 4;
            a0 += v.x * gw[(size_t)(k + 0) * NEXP + e];
            a1 += v.y * gw[(size_t)(k + 1) * NEXP + e];
            a2 += v.z * gw[(size_t)(k + 2) * NEXP + e];
            a3 += v.w * gw[(size_t)(k + 3) * NEXP + e];
        }
        sl[e] = (a0 + a1) + (a2 + a3);
    } else if (e == NEXP) {
        float a0 = 0.f, a1 = 0.f, a2 = 0.f, a3 = 0.f;
        for (int k4 = 0; k4 < HDIM / 4; k4++) {
            float4 v = x4[k4];
            int k = k4 * 4;
            a0 += v.x * sgw[k + 0];
            a1 += v.y * sgw[k + 1];
            a2 += v.z * sgw[k + 2];
            a3 += v.w * sgw[k + 3];
        }
        ssg = (a0 + a1) + (a2 + a3);
    }
    __syncthreads();
    if (threadIdx.x == 0) {
        float mx = -1e30f;
        for (int i = 0; i < NEXP; i++) mx = fmaxf(mx, sl[i]);
        float sum = 0.f;
        for (int i = 0; i < NEXP; i++) { sl[i] = expf(sl[i] - mx); sum += sl[i]; }
        for (int j = 0; j < TOPK; j++) {
            int am = 0; float bv = -1.f;
            for (int i = 0; i < NEXP; i++)
                if (sl[i] > bv) { bv = sl[i]; am = i; }
            int pos = atomicAdd(&g_cnt[am], 1);
            g_tok[am * TOKENS + pos] = t;
            g_wgt[am * TOKENS + pos] = bv / sum;
            sl[am] = -1.f;
        }
        g_gate[t] = 1.f / (1.f + expf(-ssg));
    }
}

// ============================================================================
// UP kernel: unified routed (z<60) + shared (z==60) dual GEMM
//   act = silu(X@W1)*(X@W3) [* route weight]
// Block tile 64(M) x 64(N) x 32(K), 128 thr, warps 2x2, warp tile 32x32.
// Smem: A [64][36] m-major (bank 4g+t), B [32][72] k-major (bank 8t+g),
// cp.async 2-stage double buffer, tf32 cvt.rna at fragment load.
// ============================================================================
#define UP_AF   (64 * 36)
#define UP_BF   (32 * 72)
#define UP_STG  (UP_AF + 2 * UP_BF)          // 6912 floats
#define UP_SMEM (2 * UP_STG * 4)             // 55296 bytes

__global__ __launch_bounds__(128, 4) void up_kernel(
    const float* __restrict__ X,
    const float* __restrict__ W1, const float* __restrict__ W3,
    const float* __restrict__ SW1, const float* __restrict__ SW3) {
    int e = blockIdx.z;
    int n_base = blockIdx.x * 64;
    int m_base = blockIdx.y * 64;

    int N, rows;
    const float *w1p, *w3p;
    float* outp;
    const int* tokp = nullptr;
    const float* wgtp = nullptr;
    if (e < NEXP) {
        N = IDIM;
        if (n_base >= IDIM) return;
        rows = g_cnt[e];
        if (m_base >= rows) return;
        w1p = W1 + (size_t)e * HDIM * IDIM;
        w3p = W3 + (size_t)e * HDIM * IDIM;
        outp = g_act + (size_t)e * TOKENS * IDIM;
        tokp = g_tok + e * TOKENS;
        wgtp = g_wgt + e * TOKENS;
    } else {
        N = SDIM;
        rows = TOKENS;
        w1p = SW1; w3p = SW3; outp = g_up;
    }

    extern __shared__ float smem[];
    uint32_t sbase = smem_u32(smem);
    int tid = threadIdx.x;

    // A chunk assignments: 512 16B-chunks (64 rows x 8 chunks), 4 per thread
    const float* asrc[4];
    uint32_t asz[4];
    uint32_t adst[4];
#pragma unroll
    for (int i = 0; i < 4; i++) {
        int c = i * 128 + tid;
        int r = c >> 3;       // row 0..63
        int kk = c & 7;       // 16B chunk 0..7
        adst[i] = (uint32_t)(r * 36 + kk * 4) * 4;
        int mg = m_base + r;
        if (mg < rows) {
            int s = (e < NEXP) ? tokp[mg] : mg;
            asrc[i] = X + (size_t)s * HDIM + kk * 4;
            asz[i] = 16;
        } else {
            asrc[i] = X;
            asz[i] = 0;
        }
    }
    // B chunk assignments: per matrix 512 chunks (32 k x 16 chunks), 4 per thread
    int bkk[4], bnn[4];
#pragma unroll
    for (int i = 0; i < 4; i++) {
        int c = i * 128 + tid;
        bkk[i] = c >> 4;          // 0..31
        bnn[i] = (c & 15) * 4;    // 0..60
    }

    int warp = tid >> 5, lane = tid & 31;
    int wm = (warp >> 1) * 32, wn = (warp & 1) * 32;
    int gid = lane >> 2, tig = lane & 3;

    float acc1[2][4][4], acc3[2][4][4];
#pragma unroll
    for (int a = 0; a < 2; a++)
#pragma unroll
        for (int b = 0; b < 4; b++)
#pragma unroll
            for (int c = 0; c < 4; c++) { acc1[a][b][c] = 0.f; acc3[a][b][c] = 0.f; }

    // stage loader
    auto load_stage = [&](int st, int k0) {
        uint32_t sa = sbase + (uint32_t)(st * UP_STG) * 4;
#pragma unroll
        for (int i = 0; i < 4; i++) cpa16(sa + adst[i], asrc[i] + k0, asz[i]);
        uint32_t sb1 = sa + UP_AF * 4;
        uint32_t sb3 = sb1 + UP_BF * 4;
#pragma unroll
        for (int i = 0; i < 4; i++) {
            size_t off = (size_t)(k0 + bkk[i]) * N + n_base + bnn[i];
            uint32_t d = (uint32_t)(bkk[i] * 72 + bnn[i]) * 4;
            cpa16(sb1 + d, w1p + off, 16);
            cpa16(sb3 + d, w3p + off, 16);
        }
        cpa_commit();
    };

    int st = 0;
    load_stage(0, 0);
    for (int k0 = 0; k0 < HDIM; k0 += 32) {
        if (k0 + 32 < HDIM) { load_stage(st ^ 1, k0 + 32); cpa_wait1(); }
        else { cpa_wait0(); }
        __syncthreads();

        const float* As = smem + st * UP_STG;
        const float* B1 = As + UP_AF;
        const float* B3 = B1 + UP_BF;
#pragma unroll
        for (int kb = 0; kb < 32; kb += 8) {
            int kt = kb + tig;
            uint32_t a[2][4];
#pragma unroll
            for (int ms = 0; ms < 2; ms++) {
                const float* ap = As + (wm + ms * 16 + gid) * 36;
                a[ms][0] = f2tf(ap[kt]);
                a[ms][1] = f2tf(ap[8 * 36 + kt]);
                a[ms][2] = f2tf(ap[kt + 4]);
                a[ms][3] = f2tf(ap[8 * 36 + kt + 4]);
            }
#pragma unroll
            for (int ns = 0; ns < 4; ns++) {
                int nc = wn + ns * 8 + gid;
                uint32_t b10 = f2tf(B1[kt * 72 + nc]);
                uint32_t b11 = f2tf(B1[(kt + 4) * 72 + nc]);
                uint32_t b30 = f2tf(B3[kt * 72 + nc]);
                uint32_t b31 = f2tf(B3[(kt + 4) * 72 + nc]);
#pragma unroll
                for (int ms = 0; ms < 2; ms++) {
                    mma8(acc1[ms][ns][0], acc1[ms][ns][1], acc1[ms][ns][2], acc1[ms][ns][3],
                         a[ms][0], a[ms][1], a[ms][2], a[ms][3], b10, b11);
                    mma8(acc3[ms][ns][0], acc3[ms][ns][1], acc3[ms][ns][2], acc3[ms][ns][3],
                         a[ms][0], a[ms][1], a[ms][2], a[ms][3], b30, b31);
                }
            }
        }
        __syncthreads();
        st ^= 1;
    }

    // epilogue: silu(p1) * p3 [* route weight]
#pragma unroll
    for (int ms = 0; ms < 2; ms++)
#pragma unroll
        for (int ns = 0; ns < 4; ns++)
#pragma unroll
            for (int i = 0; i < 4; i++) {
                int m = m_base + wm + ms * 16 + gid + ((i & 2) ? 8 : 0);
                int n = n_base + wn + ns * 8 + tig * 2 + (i & 1);
                if (m < rows) {
                    float p1 = acc1[ms][ns][i];
                    float p3 = acc3[ms][ns][i];
                    float v = (p1 / (1.f + expf(-p1))) * p3;
                    if (e < NEXP) v *= wgtp[m];
                    outp[(size_t)m * N + n] = v;
                }
            }
}

// ============================================================================
// DOWN kernel: unified routed (z<60) + shared (z==60) GEMM, atomic scatter out
// Block tile 64(M) x 128(N) x 32(K), 128 thr, warps 2x2, warp tile 32x64.
// Smem: A [64][36], B [32][136] (bank 8t+g).
// ============================================================================
#define DN_AF   (64 * 36)
#define DN_BF   (32 * 136)
#define DN_STG  (DN_AF + DN_BF)              // 6656 floats
#define DN_SMEM (2 * DN_STG * 4)             // 53248 bytes

__global__ __launch_bounds__(128, 4) void down_kernel(
    const float* __restrict__ W2,   // [E, I, H]
    const float* __restrict__ SW2,  // [S, H]
    float* __restrict__ out) {
    const int N = HDIM;
    int e = blockIdx.z;
    int n_base = blockIdx.x * 128;
    int m_base = blockIdx.y * 64;

    int K, rows;
    const float* Ap;
    const float* wp;
    const int* tokp = nullptr;
    if (e < NEXP) {
        K = IDIM;
        rows = g_cnt[e];
        if (m_base >= rows) return;
        Ap = g_act + (size_t)e * TOKENS * IDIM;
        wp = W2 + (size_t)e * IDIM * HDIM;
        tokp = g_tok + e * TOKENS;
    } else {
        K = SDIM;
        rows = TOKENS;
        Ap = g_up;
        wp = SW2;
    }

    extern __shared__ float smem[];
    uint32_t sbase = smem_u32(smem);
    int tid = threadIdx.x;

    const float* asrc[4];
    uint32_t asz[4];
    uint32_t adst[4];
#pragma unroll
    for (int i = 0; i < 4; i++) {
        int c = i * 128 + tid;
        int r = c >> 3;
        int kk = c & 7;
        adst[i] = (uint32_t)(r * 36 + kk * 4) * 4;
        int mg = m_base + r;
        if (mg < rows) {
            asrc[i] = Ap + (size_t)mg * K + kk * 4;
            asz[i] = 16;
        } else {
            asrc[i] = Ap;
            asz[i] = 0;
        }
    }
    // B chunks: 32 k x 32 chunks = 1024, 8 per thread
    int bkk[8], bnn[8];
#pragma unroll
    for (int i = 0; i < 8; i++) {
        int c = i * 128 + tid;
        bkk[i] = c >> 5;          // 0..31
        bnn[i] = (c & 31) * 4;    // 0..124
    }

    int warp = tid >> 5, lane = tid & 31;
    int wm = (warp >> 1) * 32, wn = (warp & 1) * 64;
    int gid = lane >> 2, tig = lane & 3;

    float acc[2][8][4];
#pragma unroll
    for (int a = 0; a < 2; a++)
#pragma unroll
        for (int b = 0; b < 8; b++)
#pragma unroll
            for (int c = 0; c < 4; c++) acc[a][b][c] = 0.f;

    auto load_stage = [&](int st, int k0) {
        uint32_t sa = sbase + (uint32_t)(st * DN_STG) * 4;
#pragma unroll
        for (int i = 0; i < 4; i++) cpa16(sa + adst[i], asrc[i] + k0, asz[i]);
        uint32_t sb = sa + DN_AF * 4;
#pragma unroll
        for (int i = 0; i < 8; i++) {
            size_t off = (size_t)(k0 + bkk[i]) * N + n_base + bnn[i];
            cpa16(sb + (uint32_t)(bkk[i] * 136 + bnn[i]) * 4, wp + off, 16);
        }
        cpa_commit();
    };

    int st = 0;
    load_stage(0, 0);
    for (int k0 = 0; k0 < K; k0 += 32) {
        if (k0 + 32 < K) { load_stage(st ^ 1, k0 + 32); cpa_wait1(); }
        else { cpa_wait0(); }
        __syncthreads();

        const float* As = smem + st * DN_STG;
        const float* Bs = As + DN_AF;
#pragma unroll
        for (int kb = 0; kb < 32; kb += 8) {
            int kt = kb + tig;
            uint32_t a[2][4];
#pragma unroll
            for (int ms = 0; ms < 2; ms++) {
                const float* ap = As + (wm + ms * 16 + gid) * 36;
                a[ms][0] = f2tf(ap[kt]);
                a[ms][1] = f2tf(ap[8 * 36 + kt]);
                a[ms][2] = f2tf(ap[kt + 4]);
                a[ms][3] = f2tf(ap[8 * 36 + kt + 4]);
            }
#pragma unroll
            for (int ns = 0; ns < 8; ns++) {
                int nc = wn + ns * 8 + gid;
                uint32_t b0 = f2tf(Bs[kt * 136 + nc]);
                uint32_t b1 = f2tf(Bs[(kt + 4) * 136 + nc]);
#pragma unroll
                for (int ms = 0; ms < 2; ms++) {
                    mma8(acc[ms][ns][0], acc[ms][ns][1], acc[ms][ns][2], acc[ms][ns][3],
                         a[ms][0], a[ms][1], a[ms][2], a[ms][3], b0, b1);
                }
            }
        }
        __syncthreads();
        st ^= 1;
    }

#pragma unroll
    for (int ms = 0; ms < 2; ms++)
#pragma unroll
        for (int ns = 0; ns < 8; ns++)
#pragma unroll
            for (int i = 0; i < 4; i++) {
                int m = m_base + wm + ms * 16 + gid + ((i & 2) ? 8 : 0);
                int n = n_base + wn + ns * 8 + tig * 2 + (i & 1);
                if (m < rows) {
                    float v = acc[ms][ns][i];
                    if (e < NEXP) {
                        atomicAdd(&out[(size_t)tokp[m] * N + n], v);
                    } else {
                        atomicAdd(&out[(size_t)m * N + n], g_gate[m] * v);
                    }
                }
            }
}

// ---------------- launch ----------------
extern "C" void kernel_launch(void* const* d_in, const int* in_sizes, int n_in,
                              void* d_out, int out_size) {
    const float* x   = (const float*)d_in[0];
    const float* gw  = (const float*)d_in[1];
    const float* w1  = (const float*)d_in[2];
    const float* w3  = (const float*)d_in[3];
    const float* w2  = (const float*)d_in[4];
    const float* sw1 = (const float*)d_in[5];
    const float* sw3 = (const float*)d_in[6];
    const float* sw2 = (const float*)d_in[7];
    const float* sgw = (const float*)d_in[8];
    float* out = (float*)d_out;

    static bool attr_set = false;
    if (!attr_set) {
        cudaFuncSetAttribute(up_kernel, cudaFuncAttributeMaxDynamicSharedMemorySize, UP_SMEM);
        cudaFuncSetAttribute(down_kernel, cudaFuncAttributeMaxDynamicSharedMemorySize, DN_SMEM);
        attr_set = true;
    }

    zero_kernel<<<(TOKENS * HDIM + 255) / 256, 256>>>(out, TOKENS * HDIM);
    router_kernel<<<TOKENS, 64>>>(x, gw, sgw);

    // unified up: routed experts (z<60, N=IDIM) + shared expert (z=60, N=SDIM)
    up_kernel<<<dim3(SDIM / 64, TOKENS / 64, NEXP + 1), 128, UP_SMEM>>>(x, w1, w3, sw1, sw3);

    // unified down: routed (K=IDIM) + shared (K=SDIM), atomic accumulate into out
    down_kernel<<<dim3(HDIM / 128, TOKENS / 64, NEXP + 1), 128, DN_SMEM>>>(w2, sw2, out);
}